// round 5
// baseline (speedup 1.0000x reference)
#include <cuda_runtime.h>
#include <cuda_fp16.h>
#include <cstdint>

#define UNITS 128
#define QDIM 256
#define VDIM 256
#define BATCH 128
#define SEQ 4096
#define TILE_M 128
#define N_TILES 4096
#define GRID_A 152

__device__ float g_qproj[BATCH*UNITS];
__device__ __half g_bhi[UNITS*VDIM];
__device__ __half g_blo[UNITS*VDIM];
__device__ float g_escore[BATCH*SEQ];
__device__ float g_psum[N_TILES];
__device__ float g_inv[BATCH];
__device__ float g_pctx[N_TILES*VDIM];

/* smem map (bytes) */
#define SM_BH 0
#define SM_BL 65536
#define SM_AH 131072
#define SM_AL 147456
#define SM_QROW 163840
#define SM_WV 164352
#define SM_SRED 164864
#define SM_WRED 165888
#define SM_TOTAL 165952

#define LDSM4(f, addr) asm volatile( \
  "ldmatrix.sync.aligned.m8n8.x4.shared.b16 {%0,%1,%2,%3}, [%4];" \
  : "=r"((f)[0]),"=r"((f)[1]),"=r"((f)[2]),"=r"((f)[3]) : "r"(addr))

#define MMA(dd, aa, b0, b1) asm volatile( \
  "mma.sync.aligned.m16n8k16.row.col.f32.f16.f16.f32 {%0,%1,%2,%3}, {%4,%5,%6,%7}, {%8,%9}, {%0,%1,%2,%3};" \
  : "+f"((dd)[0]),"+f"((dd)[1]),"+f"((dd)[2]),"+f"((dd)[3]) \
  : "r"((aa)[0]),"r"((aa)[1]),"r"((aa)[2]),"r"((aa)[3]),"r"(b0),"r"(b1))

__device__ __forceinline__ uint32_t h2u(__half2 h){ return *(uint32_t*)&h; }

/* FMA-only tanh (no MUFU): abs err < 2e-5 */
__device__ __forceinline__ float ftanh(float x){
    float xc = fminf(10.f, fmaxf(-10.f, x));
    float t = fmaf(xc, 2.885390082f, 12582912.f);
    float f = fmaf(xc, 2.885390082f, 12582912.f - t);
    int n = __float_as_int(t) - 0x4B400000;
    float p = 1.3333558e-3f;
    p = fmaf(p, f, 9.6181291e-3f);
    p = fmaf(p, f, 5.5504109e-2f);
    p = fmaf(p, f, 2.4022651e-1f);
    p = fmaf(p, f, 6.9314718e-1f);
    p = fmaf(p, f, 1.0f);
    float E = p * __int_as_float((n + 127) << 23);  /* e^{2x} */
    float D = 1.0f + E;
    float r = __uint_as_float(0x7EF311C3u - __float_as_uint(D));
    r = r * (2.0f - D*r);
    r = r * (2.0f - D*r);
    return fmaf(-2.0f, r, 1.0f);
}

__global__ void k_prep(const float* __restrict__ q, const float* __restrict__ W1,
                       const float* __restrict__ b1, const float* __restrict__ W2,
                       const float* __restrict__ b2){
    if (blockIdx.x < BATCH){
        int b = blockIdx.x, u = threadIdx.x;
        float acc = b1[u] + b2[u];
        #pragma unroll 8
        for (int k = 0; k < QDIM; k++) acc = fmaf(q[b*QDIM+k], W1[k*UNITS+u], acc);
        g_qproj[b*UNITS+u] = acc;
    } else {
        for (int i = threadIdx.x; i < UNITS*VDIM; i += 128){
            int u = i >> 8, k = i & 255;
            float w = W2[k*UNITS+u];
            __half h = __float2half_rn(w);
            g_bhi[u*VDIM+k] = h;
            g_blo[u*VDIM+k] = __float2half_rn(w - __half2float(h));
        }
    }
}

__global__ void __launch_bounds__(256,1)
k_scores(const float* __restrict__ values, const float* __restrict__ Wv, const float* __restrict__ bv){
    extern __shared__ char smem[];
    const int tid = threadIdx.x;
    const int lane = tid & 31;
    const int wid = tid >> 5;
    const int warp_m = wid & 3;   /* 4 groups x 32 rows */
    const int warp_n = wid >> 2;  /* 2 groups x 64 units */

    uint32_t sbase;
    asm("{ .reg .u64 t; cvta.to.shared.u64 t, %1; cvt.u32.u64 %0, t; }":"=r"(sbase):"l"(smem));

    /* stage B hi/lo into smem: [u][k] rows of 512B, XOR-swizzled 16B granules */
    #pragma unroll
    for (int j = 0; j < 16; j++){
        int G = j*256 + tid;
        int u = G >> 5, g = G & 31;
        int off = u*512 + ((g ^ (u&7))<<4);
        *(uint4*)(smem + SM_BH + off) = ((const uint4*)g_bhi)[G];
        *(uint4*)(smem + SM_BL + off) = ((const uint4*)g_blo)[G];
    }
    if (tid < UNITS) ((float*)(smem+SM_WV))[tid] = Wv[tid];
    const float bvv = bv[0];
    float* qrow = (float*)(smem+SM_QROW);
    float* wvs  = (float*)(smem+SM_WV);
    float* sred = (float*)(smem+SM_SRED);
    float* wred = (float*)(smem+SM_WRED);

    /* per-lane ldmatrix address precompute */
    uint32_t a_base[2]; int a_r7[2];
    #pragma unroll
    for (int mf = 0; mf < 2; mf++){
        int r = warp_m*32 + mf*16 + ((lane>>3)&1)*8 + (lane&7);
        a_base[mf] = sbase + SM_AH + r*128;
        a_r7[mf] = r & 7;
    }
    uint32_t b_base[4]; int b_n7[4];
    #pragma unroll
    for (int nf2 = 0; nf2 < 4; nf2++){
        int n = warp_n*64 + nf2*16 + (lane>>4)*8 + (lane&7);
        b_base[nf2] = sbase + SM_BH + n*512;
        b_n7[nf2] = n & 7;
    }
    const int gA_l = (lane>>4);
    const int gB_l = ((lane>>3)&1);
    const int srow = tid >> 1;
    const int shalf = tid & 1;

    float4 v[8];
    for (int tile = blockIdx.x; tile < N_TILES; tile += gridDim.x){
        const int b = tile >> 5, s0 = (tile & 31) * TILE_M;
        const float* vp = values + ((size_t)(b*SEQ + s0 + srow))*VDIM + shalf*32;
        #pragma unroll
        for (int j = 0; j < 8; j++) v[j] = ((const float4*)vp)[j];
        if (tid < 128) qrow[tid] = g_qproj[b*UNITS + tid];
        float d[2][8][4] = {};
        __syncthreads();

        #pragma unroll 1
        for (int kc = 0; kc < 4; kc++){
            /* convert chunk to fp16 hi/lo, store swizzled */
            #pragma unroll
            for (int i = 0; i < 4; i++){
                float4 va = v[2*i], vb2 = v[2*i+1];
                __half2 h0 = __floats2half2_rn(va.x, va.y);
                __half2 h1 = __floats2half2_rn(va.z, va.w);
                __half2 h2 = __floats2half2_rn(vb2.x, vb2.y);
                __half2 h3 = __floats2half2_rn(vb2.z, vb2.w);
                float2 f0 = __half22float2(h0), f1 = __half22float2(h1);
                float2 f2 = __half22float2(h2), f3 = __half22float2(h3);
                __half2 l0 = __floats2half2_rn(va.x-f0.x, va.y-f0.y);
                __half2 l1 = __floats2half2_rn(va.z-f1.x, va.w-f1.y);
                __half2 l2 = __floats2half2_rn(vb2.x-f2.x, vb2.y-f2.y);
                __half2 l3 = __floats2half2_rn(vb2.z-f3.x, vb2.w-f3.y);
                int g = shalf*4 + i;
                int off = srow*128 + ((g ^ (srow&7))<<4);
                *(uint4*)(smem + SM_AH + off) = make_uint4(h2u(h0),h2u(h1),h2u(h2),h2u(h3));
                *(uint4*)(smem + SM_AL + off) = make_uint4(h2u(l0),h2u(l1),h2u(l2),h2u(l3));
            }
            __syncthreads();
            if (kc < 3){
                const float* vp2 = vp + (kc+1)*64;
                #pragma unroll
                for (int j = 0; j < 8; j++) v[j] = ((const float4*)vp2)[j];
            }
            /* MMA over this chunk: 4 k16 steps */
            #pragma unroll
            for (int ks = 0; ks < 4; ks++){
                uint32_t ah[2][4], al[2][4];
                #pragma unroll
                for (int mf = 0; mf < 2; mf++){
                    int gA = ks*2 + gA_l;
                    uint32_t ad = a_base[mf] + ((gA ^ a_r7[mf])<<4);
                    LDSM4(ah[mf], ad);
                    LDSM4(al[mf], ad + (SM_AL - SM_AH));
                }
                #pragma unroll
                for (int nf2 = 0; nf2 < 4; nf2++){
                    int gB = kc*8 + ks*2 + gB_l;
                    uint32_t bd = b_base[nf2] + ((gB ^ b_n7[nf2])<<4);
                    uint32_t bh[4], bl[4];
                    LDSM4(bh, bd);
                    LDSM4(bl, bd + (SM_BL - SM_BH));
                    #pragma unroll
                    for (int mf = 0; mf < 2; mf++){
                        MMA(d[mf][2*nf2],   ah[mf], bh[0], bh[1]);
                        MMA(d[mf][2*nf2],   al[mf], bh[0], bh[1]);
                        MMA(d[mf][2*nf2],   ah[mf], bl[0], bl[1]);
                        MMA(d[mf][2*nf2+1], ah[mf], bh[2], bh[3]);
                        MMA(d[mf][2*nf2+1], al[mf], bh[2], bh[3]);
                        MMA(d[mf][2*nf2+1], ah[mf], bl[2], bl[3]);
                    }
                }
            }
            __syncthreads();
        }

        /* epilogue: wv . tanh(d + qproj) */
        float part[4] = {0.f,0.f,0.f,0.f};
        #pragma unroll
        for (int mf = 0; mf < 2; mf++)
            #pragma unroll
            for (int nf = 0; nf < 8; nf++)
                #pragma unroll
                for (int e = 0; e < 4; e++){
                    int col = warp_n*64 + nf*8 + (lane&3)*2 + (e&1);
                    float pre = d[mf][nf][e] + qrow[col];
                    int pi = mf*2 + (e>>1);
                    part[pi] = fmaf(wvs[col], ftanh(pre), part[pi]);
                }
        #pragma unroll
        for (int p = 0; p < 4; p++){
            part[p] += __shfl_xor_sync(0xffffffffu, part[p], 1);
            part[p] += __shfl_xor_sync(0xffffffffu, part[p], 2);
        }
        if ((lane & 3) == 0){
            #pragma unroll
            for (int mf = 0; mf < 2; mf++)
                #pragma unroll
                for (int rh = 0; rh < 2; rh++){
                    int row = warp_m*32 + mf*16 + (lane>>2) + rh*8;
                    sred[warp_n*128 + row] = part[mf*2+rh];
                }
        }
        __syncthreads();
        if (tid < 128){
            float e = __expf(sred[tid] + sred[128+tid] + bvv);
            g_escore[b*SEQ + s0 + tid] = e;
            #pragma unroll
            for (int o = 16; o; o >>= 1) e += __shfl_xor_sync(0xffffffffu, e, o);
            if (lane == 0) wred[tid>>5] = e;
        }
        __syncthreads();
        if (tid == 0) g_psum[tile] = wred[0]+wred[1]+wred[2]+wred[3];
        __syncthreads();
    }
}

__global__ void k_inv(){
    int b = threadIdx.x;
    float s = 0.f;
    #pragma unroll
    for (int t = 0; t < 32; t++) s += g_psum[b*32 + t];
    g_inv[b] = 1.f / s;
}

__global__ void __launch_bounds__(256)
k_ctx(const float* __restrict__ values, float* __restrict__ outw){
    __shared__ float swt[TILE_M];
    __shared__ float4 sacc[4][64];
    int tile = blockIdx.x;
    int b = tile >> 5, s0 = (tile & 31) * TILE_M;
    int tid = threadIdx.x;
    if (tid < TILE_M){
        float w = g_escore[b*SEQ + s0 + tid] * g_inv[b];
        swt[tid] = w;
        outw[b*SEQ + s0 + tid] = w;
    }
    __syncthreads();
    int d4 = tid & 63, sq = tid >> 6;
    const float4* vb = (const float4*)(values + ((size_t)(b*SEQ + s0 + sq*32))*VDIM) + d4;
    float4 acc = {0.f,0.f,0.f,0.f};
    #pragma unroll 8
    for (int s = 0; s < 32; s++){
        float4 vv = vb[(size_t)s*64];
        float w = swt[sq*32 + s];
        acc.x = fmaf(w, vv.x, acc.x);
        acc.y = fmaf(w, vv.y, acc.y);
        acc.z = fmaf(w, vv.z, acc.z);
        acc.w = fmaf(w, vv.w, acc.w);
    }
    sacc[sq][d4] = acc;
    __syncthreads();
    if (tid < 64){
        float4 a0 = sacc[0][tid], a1 = sacc[1][tid], a2 = sacc[2][tid], a3 = sacc[3][tid];
        float4 r;
        r.x = (a0.x+a1.x) + (a2.x+a3.x);
        r.y = (a0.y+a1.y) + (a2.y+a3.y);
        r.z = (a0.z+a1.z) + (a2.z+a3.z);
        r.w = (a0.w+a1.w) + (a2.w+a3.w);
        ((float4*)g_pctx)[tile*64 + tid] = r;
    }
}

__global__ void k_red(float* __restrict__ outc){
    int b = blockIdx.x, d = threadIdx.x;
    float a = 0.f;
    #pragma unroll
    for (int t = 0; t < 32; t++) a += g_pctx[(b*32 + t)*VDIM + d];
    outc[b*VDIM + d] = a;
}

extern "C" void kernel_launch(void* const* d_in, const int* in_sizes, int n_in,
                              void* d_out, int out_size){
    (void)in_sizes; (void)n_in; (void)out_size;
    const float* query  = (const float*)d_in[0];
    const float* values = (const float*)d_in[1];
    const float* W1 = (const float*)d_in[2];
    const float* b1 = (const float*)d_in[3];
    const float* W2 = (const float*)d_in[4];
    const float* b2 = (const float*)d_in[5];
    const float* Wv = (const float*)d_in[6];
    const float* bv = (const float*)d_in[7];
    float* out = (float*)d_out;
    cudaFuncSetAttribute(k_scores, cudaFuncAttributeMaxDynamicSharedMemorySize, SM_TOTAL);
    k_prep<<<BATCH + 1, 128>>>(query, W1, b1, W2, b2);
    k_scores<<<GRID_A, 256, SM_TOTAL>>>(values, Wv, bv);
    k_inv<<<1, BATCH>>>();
    k_ctx<<<N_TILES, 256>>>(values, out + BATCH*VDIM);
    k_red<<<BATCH, VDIM>>>(out);
}

// round 6
// speedup vs baseline: 1.2790x; 1.2790x over previous
#include <cuda_runtime.h>
#include <cuda_fp16.h>
#include <cstdint>

#define UNITS 128
#define QDIM 256
#define VDIM 256
#define BATCH 128
#define SEQ 4096
#define TILE_M 128
#define N_TILES 4096
#define GRID_A 152

__device__ float g_qproj[BATCH*UNITS];
__device__ __half g_bhi[UNITS*VDIM];
__device__ __half g_blo[UNITS*VDIM];
__device__ float g_escore[BATCH*SEQ];
__device__ float g_psum[N_TILES];
__device__ float g_inv[BATCH];
__device__ float g_pctx[N_TILES*VDIM];

/* smem map (bytes) */
#define SM_BH 0
#define SM_BL 65536
#define SM_A0 131072
#define SM_A1 147456
#define SM_QROW 163840
#define SM_WV 164352
#define SM_SRED 164864
#define SM_WRED 165888
#define SM_TOTAL 165952

#define LDSM4(f, addr) asm volatile( \
  "ldmatrix.sync.aligned.m8n8.x4.shared.b16 {%0,%1,%2,%3}, [%4];" \
  : "=r"((f)[0]),"=r"((f)[1]),"=r"((f)[2]),"=r"((f)[3]) : "r"(addr))

#define MMA(dd, aa, b0, b1) asm volatile( \
  "mma.sync.aligned.m16n8k16.row.col.f32.f16.f16.f32 {%0,%1,%2,%3}, {%4,%5,%6,%7}, {%8,%9}, {%0,%1,%2,%3};" \
  : "+f"((dd)[0]),"+f"((dd)[1]),"+f"((dd)[2]),"+f"((dd)[3]) \
  : "r"((aa)[0]),"r"((aa)[1]),"r"((aa)[2]),"r"((aa)[3]),"r"(b0),"r"(b1))

__device__ __forceinline__ uint32_t h2u(__half2 h){ return *(uint32_t*)&h; }

/* MUFU tanh: 1 - 2/(1+e^{2x}); exact at +-inf, rel err ~1e-6 */
__device__ __forceinline__ float ftanh(float x){
    float e = __expf(2.0f * x);
    return 1.0f - __fdividef(2.0f, 1.0f + e);
}

__global__ void k_prep(const float* __restrict__ q, const float* __restrict__ W1,
                       const float* __restrict__ b1, const float* __restrict__ W2,
                       const float* __restrict__ b2){
    if (blockIdx.x < BATCH){
        int b = blockIdx.x, u = threadIdx.x;
        float acc = b1[u] + b2[u];
        #pragma unroll 8
        for (int k = 0; k < QDIM; k++) acc = fmaf(q[b*QDIM+k], W1[k*UNITS+u], acc);
        g_qproj[b*UNITS+u] = acc;
    } else {
        for (int i = threadIdx.x; i < UNITS*VDIM; i += 128){
            int u = i >> 8, k = i & 255;
            float w = W2[k*UNITS+u];
            __half h = __float2half_rn(w);
            g_bhi[u*VDIM+k] = h;
            g_blo[u*VDIM+k] = __float2half_rn(w - __half2float(h));
        }
    }
}

__global__ void __launch_bounds__(512,1)
k_scores(const float* __restrict__ values, const float* __restrict__ Wv, const float* __restrict__ bv){
    extern __shared__ char smem[];
    const int tid = threadIdx.x;
    const int lane = tid & 31;
    const int wid = tid >> 5;
    const int warp_m = wid & 7;   /* 8 groups x 16 rows */
    const int warp_n = wid >> 3;  /* 2 groups x 64 units */

    uint32_t sbase;
    asm("{ .reg .u64 t; cvta.to.shared.u64 t, %1; cvt.u32.u64 %0, t; }":"=r"(sbase):"l"(smem));

    /* stage B hi/lo into smem: [u][k] rows of 512B, XOR-swizzled 16B granules */
    #pragma unroll
    for (int j = 0; j < 8; j++){
        int G = j*512 + tid;
        int u = G >> 5, g = G & 31;
        int off = u*512 + ((g ^ (u&7))<<4);
        *(uint4*)(smem + SM_BH + off) = ((const uint4*)g_bhi)[G];
        *(uint4*)(smem + SM_BL + off) = ((const uint4*)g_blo)[G];
    }
    if (tid < UNITS) ((float*)(smem+SM_WV))[tid] = Wv[tid];
    const float bvv = bv[0];
    float* qrow = (float*)(smem+SM_QROW);
    float* wvs  = (float*)(smem+SM_WV);
    float* sred = (float*)(smem+SM_SRED);
    float* wred = (float*)(smem+SM_WRED);

    /* ldmatrix address precompute */
    const int a_r = warp_m*16 + ((lane>>3)&1)*8 + (lane&7);
    const uint32_t a_base0 = sbase + SM_A0 + a_r*128;
    const int a_r7 = a_r & 7;
    const int gA_l = (lane>>4);
    uint32_t b_base[4]; int b_n7[4];
    #pragma unroll
    for (int nf2 = 0; nf2 < 4; nf2++){
        int n = warp_n*64 + nf2*16 + (lane>>4)*8 + (lane&7);
        b_base[nf2] = sbase + SM_BH + n*512;
        b_n7[nf2] = n & 7;
    }
    const int gB_l = ((lane>>3)&1);
    const int srow = tid >> 2;
    const int sq = tid & 3;

    for (int tile = blockIdx.x; tile < N_TILES; tile += gridDim.x){
        const int b = tile >> 5, s0 = (tile & 31) * TILE_M;
        const float* vp = values + ((size_t)(b*SEQ + s0 + srow))*VDIM + sq*16;
        float4 v[4];
        #pragma unroll
        for (int j = 0; j < 4; j++) v[j] = ((const float4*)vp)[j];
        if (tid < 128) qrow[tid] = g_qproj[b*UNITS + tid];
        float d[8][4] = {};
        /* convert chunk 0 into buf 0 */
        #pragma unroll
        for (int i = 0; i < 2; i++){
            float4 p0 = v[2*i], p1 = v[2*i+1];
            __half2 h0=__floats2half2_rn(p0.x,p0.y), h1=__floats2half2_rn(p0.z,p0.w);
            __half2 h2=__floats2half2_rn(p1.x,p1.y), h3=__floats2half2_rn(p1.z,p1.w);
            int off = srow*128 + (((sq*2+i)^(srow&7))<<4);
            *(uint4*)(smem + SM_A0 + off) = make_uint4(h2u(h0),h2u(h1),h2u(h2),h2u(h3));
        }

        #pragma unroll
        for (int kc = 0; kc < 4; kc++){
            __syncthreads();
            /* prefetch next chunk */
            if (kc < 3){
                const float* vp2 = vp + (kc+1)*64;
                #pragma unroll
                for (int j = 0; j < 4; j++) v[j] = ((const float4*)vp2)[j];
            }
            /* MMA over current chunk from buf[kc&1] */
            const uint32_t abase = a_base0 + (uint32_t)((kc&1)*(SM_A1-SM_A0));
            #pragma unroll
            for (int ks = 0; ks < 4; ks++){
                uint32_t a[4];
                int gA = ks*2 + gA_l;
                LDSM4(a, abase + ((gA ^ a_r7)<<4));
                #pragma unroll
                for (int nf2 = 0; nf2 < 4; nf2++){
                    int gB = kc*8 + ks*2 + gB_l;
                    uint32_t bd = b_base[nf2] + ((gB ^ b_n7[nf2])<<4);
                    uint32_t bh[4], bl[4];
                    LDSM4(bh, bd);
                    LDSM4(bl, bd + (SM_BL - SM_BH));
                    MMA(d[2*nf2],   a, bh[0], bh[1]);
                    MMA(d[2*nf2],   a, bl[0], bl[1]);
                    MMA(d[2*nf2+1], a, bh[2], bh[3]);
                    MMA(d[2*nf2+1], a, bl[2], bl[3]);
                }
            }
            /* convert next chunk into other buffer */
            if (kc < 3){
                char* buf = smem + ((kc&1) ? SM_A0 : SM_A1);
                #pragma unroll
                for (int i = 0; i < 2; i++){
                    float4 p0 = v[2*i], p1 = v[2*i+1];
                    __half2 h0=__floats2half2_rn(p0.x,p0.y), h1=__floats2half2_rn(p0.z,p0.w);
                    __half2 h2=__floats2half2_rn(p1.x,p1.y), h3=__floats2half2_rn(p1.z,p1.w);
                    int off = srow*128 + (((sq*2+i)^(srow&7))<<4);
                    *(uint4*)(buf + off) = make_uint4(h2u(h0),h2u(h1),h2u(h2),h2u(h3));
                }
            }
        }

        /* epilogue: wv . tanh(d + qproj) */
        float part[2] = {0.f, 0.f};
        #pragma unroll
        for (int nf = 0; nf < 8; nf++)
            #pragma unroll
            for (int e = 0; e < 4; e++){
                int col = warp_n*64 + nf*8 + (lane&3)*2 + (e&1);
                float pre = d[nf][e] + qrow[col];
                part[e>>1] = fmaf(wvs[col], ftanh(pre), part[e>>1]);
            }
        #pragma unroll
        for (int p = 0; p < 2; p++){
            part[p] += __shfl_xor_sync(0xffffffffu, part[p], 1);
            part[p] += __shfl_xor_sync(0xffffffffu, part[p], 2);
        }
        if ((lane & 3) == 0){
            #pragma unroll
            for (int p = 0; p < 2; p++){
                int row = warp_m*16 + (lane>>2) + p*8;
                sred[warp_n*128 + row] = part[p];
            }
        }
        __syncthreads();
        if (tid < 128){
            float e = __expf(sred[tid] + sred[128+tid] + bvv);
            g_escore[b*SEQ + s0 + tid] = e;
            #pragma unroll
            for (int o = 16; o; o >>= 1) e += __shfl_xor_sync(0xffffffffu, e, o);
            if (lane == 0) wred[tid>>5] = e;
        }
        __syncthreads();
        if (tid == 0) g_psum[tile] = wred[0]+wred[1]+wred[2]+wred[3];
    }
}

__global__ void k_inv(){
    int b = threadIdx.x;
    float s = 0.f;
    #pragma unroll
    for (int t = 0; t < 32; t++) s += g_psum[b*32 + t];
    g_inv[b] = 1.f / s;
}

__global__ void __launch_bounds__(256)
k_ctx(const float* __restrict__ values, float* __restrict__ outw){
    __shared__ float swt[TILE_M];
    __shared__ float4 sacc[4][64];
    int tile = blockIdx.x;
    int b = tile >> 5, s0 = (tile & 31) * TILE_M;
    int tid = threadIdx.x;
    if (tid < TILE_M){
        float w = g_escore[b*SEQ + s0 + tid] * g_inv[b];
        swt[tid] = w;
        outw[b*SEQ + s0 + tid] = w;
    }
    __syncthreads();
    int d4 = tid & 63, sq = tid >> 6;
    const float4* vb = (const float4*)(values + ((size_t)(b*SEQ + s0 + sq*32))*VDIM) + d4;
    float4 acc = {0.f,0.f,0.f,0.f};
    #pragma unroll 8
    for (int s = 0; s < 32; s++){
        float4 vv = vb[(size_t)s*64];
        float w = swt[sq*32 + s];
        acc.x = fmaf(w, vv.x, acc.x);
        acc.y = fmaf(w, vv.y, acc.y);
        acc.z = fmaf(w, vv.z, acc.z);
        acc.w = fmaf(w, vv.w, acc.w);
    }
    sacc[sq][d4] = acc;
    __syncthreads();
    if (tid < 64){
        float4 a0 = sacc[0][tid], a1 = sacc[1][tid], a2 = sacc[2][tid], a3 = sacc[3][tid];
        float4 r;
        r.x = (a0.x+a1.x) + (a2.x+a3.x);
        r.y = (a0.y+a1.y) + (a2.y+a3.y);
        r.z = (a0.z+a1.z) + (a2.z+a3.z);
        r.w = (a0.w+a1.w) + (a2.w+a3.w);
        ((float4*)g_pctx)[tile*64 + tid] = r;
    }
}

__global__ void k_red(float* __restrict__ outc){
    int b = blockIdx.x, d = threadIdx.x;
    float a = 0.f;
    #pragma unroll
    for (int t = 0; t < 32; t++) a += g_pctx[(b*32 + t)*VDIM + d];
    outc[b*VDIM + d] = a;
}

extern "C" void kernel_launch(void* const* d_in, const int* in_sizes, int n_in,
                              void* d_out, int out_size){
    (void)in_sizes; (void)n_in; (void)out_size;
    const float* query  = (const float*)d_in[0];
    const float* values = (const float*)d_in[1];
    const float* W1 = (const float*)d_in[2];
    const float* b1 = (const float*)d_in[3];
    const float* W2 = (const float*)d_in[4];
    const float* b2 = (const float*)d_in[5];
    const float* Wv = (const float*)d_in[6];
    const float* bv = (const float*)d_in[7];
    float* out = (float*)d_out;
    cudaFuncSetAttribute(k_scores, cudaFuncAttributeMaxDynamicSharedMemorySize, SM_TOTAL);
    k_prep<<<BATCH + 1, 128>>>(query, W1, b1, W2, b2);
    k_scores<<<GRID_A, 512, SM_TOTAL>>>(values, Wv, bv);
    k_inv<<<1, BATCH>>>();
    k_ctx<<<N_TILES, 256>>>(values, out + BATCH*VDIM);
    k_red<<<BATCH, VDIM>>>(out);
}

// round 10
// speedup vs baseline: 1.2859x; 1.0054x over previous
#include <cuda_runtime.h>
#include <cuda_fp16.h>
#include <cstdint>

#define UNITS 128
#define QDIM 256
#define VDIM 256
#define BATCH 128
#define SEQ 4096
#define TILE_M 128
#define N_TILES 4096
#define GRID_A 152

__device__ float g_qproj[BATCH*UNITS];
__device__ __half g_bhi[UNITS*VDIM];
__device__ __half g_blo[UNITS*VDIM];
__device__ float g_escore[BATCH*SEQ];
__device__ float g_psum[N_TILES];
__device__ float g_inv[BATCH];
__device__ float g_pctx[N_TILES*VDIM];

/* smem map (bytes) */
#define SM_BH 0
#define SM_BL 65536
#define SM_A0 131072          /* 4 chunk buffers x 16384 */
#define SM_QROW 196608
#define SM_WV 197120
#define SM_SRED 197632
#define SM_WRED 198656
#define SM_SW 198720
#define SM_CTX 199232         /* 4 x 128 x float2 = 4096 */
#define SM_TOTAL 203328

#define LDSM4(f, addr) asm volatile( \
  "ldmatrix.sync.aligned.m8n8.x4.shared.b16 {%0,%1,%2,%3}, [%4];" \
  : "=r"((f)[0]),"=r"((f)[1]),"=r"((f)[2]),"=r"((f)[3]) : "r"(addr))

#define MMA(dd, aa, b0, b1) asm volatile( \
  "mma.sync.aligned.m16n8k16.row.col.f32.f16.f16.f32 {%0,%1,%2,%3}, {%4,%5,%6,%7}, {%8,%9}, {%0,%1,%2,%3};" \
  : "+f"((dd)[0]),"+f"((dd)[1]),"+f"((dd)[2]),"+f"((dd)[3]) \
  : "r"((aa)[0]),"r"((aa)[1]),"r"((aa)[2]),"r"((aa)[3]),"r"(b0),"r"(b1))

__device__ __forceinline__ uint32_t h2u(__half2 h){ return *(uint32_t*)&h; }

/* tanh via MUFU: 1 - 2/(1+e^{2x}) */
__device__ __forceinline__ float ftanh(float x){
    float e = __expf(2.0f * x);
    return 1.0f - __fdividef(2.0f, 1.0f + e);
}

__global__ void k_prep(const float* __restrict__ q, const float* __restrict__ W1,
                       const float* __restrict__ b1, const float* __restrict__ W2,
                       const float* __restrict__ b2){
    if (blockIdx.x < BATCH){
        int b = blockIdx.x, u = threadIdx.x;
        float acc = b1[u] + b2[u];
        #pragma unroll 8
        for (int k = 0; k < QDIM; k++) acc = fmaf(q[b*QDIM+k], W1[k*UNITS+u], acc);
        g_qproj[b*UNITS+u] = acc;
    } else {
        for (int i = threadIdx.x; i < UNITS*VDIM; i += 128){
            int u = i >> 8, k = i & 255;
            float w = W2[k*UNITS+u];
            __half h = __float2half_rn(w);
            g_bhi[u*VDIM+k] = h;
            g_blo[u*VDIM+k] = __float2half_rn(w - __half2float(h));
        }
    }
}

__global__ void __launch_bounds__(512,1)
k_scores(const float* __restrict__ values, const float* __restrict__ Wv, const float* __restrict__ bv){
    extern __shared__ char smem[];
    const int tid = threadIdx.x;
    const int lane = tid & 31;
    const int wid = tid >> 5;
    const int warp_m = wid & 7;   /* 8 groups x 16 rows */
    const int warp_n = wid >> 3;  /* 2 groups x 64 units */

    uint32_t sbase;
    asm("{ .reg .u64 t; cvta.to.shared.u64 t, %1; cvt.u32.u64 %0, t; }":"=r"(sbase):"l"(smem));

    /* stage B hi/lo: [u][k] rows of 512B, XOR-swizzled 16B granules */
    #pragma unroll
    for (int j = 0; j < 8; j++){
        int G = j*512 + tid;
        int u = G >> 5, g = G & 31;
        int off = u*512 + ((g ^ (u&7))<<4);
        *(uint4*)(smem + SM_BH + off) = ((const uint4*)g_bhi)[G];
        *(uint4*)(smem + SM_BL + off) = ((const uint4*)g_blo)[G];
    }
    if (tid < UNITS) ((float*)(smem+SM_WV))[tid] = Wv[tid];
    const float bvv = bv[0];
    float* qrow = (float*)(smem+SM_QROW);
    float* wvs  = (float*)(smem+SM_WV);
    float* sred = (float*)(smem+SM_SRED);
    float* wred = (float*)(smem+SM_WRED);
    float* sw   = (float*)(smem+SM_SW);
    float2* sctx = (float2*)(smem+SM_CTX);

    /* ldmatrix address precompute */
    const int a_r = warp_m*16 + ((lane>>3)&1)*8 + (lane&7);
    const uint32_t a_base0 = sbase + SM_A0 + a_r*128;
    const int a_r7 = a_r & 7;
    const int gA_l = (lane>>4);
    uint32_t b_base[4]; int b_n7[4];
    #pragma unroll
    for (int nf2 = 0; nf2 < 4; nf2++){
        int n = warp_n*64 + nf2*16 + (lane>>4)*8 + (lane&7);
        b_base[nf2] = sbase + SM_BH + n*512;
        b_n7[nf2] = n & 7;
    }
    const int gB_l = ((lane>>3)&1);
    const int srow = tid >> 2;
    const int sq = tid & 3;

    /* context-phase thread mapping: dims (2p, 2p+1), row quarter q */
    const int cq = tid >> 7, cp = tid & 127;
    const uint32_t cbase = sbase + SM_A0 + (cp>>5)*16384 + ((cp&3)<<2);
    const int cg = (cp&31) >> 2;

    for (int tile = blockIdx.x; tile < N_TILES; tile += gridDim.x){
        const int b = tile >> 5, s0 = (tile & 31) * TILE_M;
        const float* vp = values + ((size_t)(b*SEQ + s0 + srow))*VDIM + sq*16;
        float4 v[4];
        #pragma unroll
        for (int j = 0; j < 4; j++) v[j] = ((const float4*)vp)[j];
        if (tid < 128) qrow[tid] = g_qproj[b*UNITS + tid];
        float d[8][4] = {};
        /* convert chunk 0 */
        #pragma unroll
        for (int i = 0; i < 2; i++){
            float4 p0 = v[2*i], p1 = v[2*i+1];
            __half2 h0=__floats2half2_rn(p0.x,p0.y), h1=__floats2half2_rn(p0.z,p0.w);
            __half2 h2=__floats2half2_rn(p1.x,p1.y), h3=__floats2half2_rn(p1.z,p1.w);
            int off = srow*128 + (((sq*2+i)^(srow&7))<<4);
            *(uint4*)(smem + SM_A0 + off) = make_uint4(h2u(h0),h2u(h1),h2u(h2),h2u(h3));
        }

        #pragma unroll
        for (int kc = 0; kc < 4; kc++){
            __syncthreads();
            if (kc < 3){
                const float* vp2 = vp + (kc+1)*64;
                #pragma unroll
                for (int j = 0; j < 4; j++) v[j] = ((const float4*)vp2)[j];
            }
            const uint32_t abase = a_base0 + (uint32_t)(kc*16384);
            #pragma unroll
            for (int ks = 0; ks < 4; ks++){
                uint32_t a[4];
                int gA = ks*2 + gA_l;
                LDSM4(a, abase + ((gA ^ a_r7)<<4));
                #pragma unroll
                for (int nf2 = 0; nf2 < 4; nf2++){
                    int gB = kc*8 + ks*2 + gB_l;
                    uint32_t bd = b_base[nf2] + ((gB ^ b_n7[nf2])<<4);
                    uint32_t bh[4], bl[4];
                    LDSM4(bh, bd);
                    LDSM4(bl, bd + (SM_BL - SM_BH));
                    MMA(d[2*nf2],   a, bh[0], bh[1]);
                    MMA(d[2*nf2],   a, bl[0], bl[1]);
                    MMA(d[2*nf2+1], a, bh[2], bh[3]);
                    MMA(d[2*nf2+1], a, bl[2], bl[3]);
                }
            }
            if (kc < 3){
                char* buf = smem + SM_A0 + (kc+1)*16384;
                #pragma unroll
                for (int i = 0; i < 2; i++){
                    float4 p0 = v[2*i], p1 = v[2*i+1];
                    __half2 h0=__floats2half2_rn(p0.x,p0.y), h1=__floats2half2_rn(p0.z,p0.w);
                    __half2 h2=__floats2half2_rn(p1.x,p1.y), h3=__floats2half2_rn(p1.z,p1.w);
                    int off = srow*128 + (((sq*2+i)^(srow&7))<<4);
                    *(uint4*)(buf + off) = make_uint4(h2u(h0),h2u(h1),h2u(h2),h2u(h3));
                }
            }
        }

        /* epilogue: score -> e */
        float part[2] = {0.f, 0.f};
        #pragma unroll
        for (int nf = 0; nf < 8; nf++)
            #pragma unroll
            for (int e = 0; e < 4; e++){
                int col = warp_n*64 + nf*8 + (lane&3)*2 + (e&1);
                float pre = d[nf][e] + qrow[col];
                part[e>>1] = fmaf(wvs[col], ftanh(pre), part[e>>1]);
            }
        #pragma unroll
        for (int p = 0; p < 2; p++){
            part[p] += __shfl_xor_sync(0xffffffffu, part[p], 1);
            part[p] += __shfl_xor_sync(0xffffffffu, part[p], 2);
        }
        if ((lane & 3) == 0){
            #pragma unroll
            for (int p = 0; p < 2; p++){
                int row = warp_m*16 + (lane>>2) + p*8;
                sred[warp_n*128 + row] = part[p];
            }
        }
        __syncthreads();
        if (tid < 128){
            float e = __expf(sred[tid] + sred[128+tid] + bvv);
            g_escore[b*SEQ + s0 + tid] = e;
            sw[tid] = e;
            #pragma unroll
            for (int o = 16; o; o >>= 1) e += __shfl_xor_sync(0xffffffffu, e, o);
            if (lane == 0) wred[tid>>5] = e;
        }
        __syncthreads();

        /* fused context: pctx[d] = sum_r e_r * v_hi[r][d] (from A smem) */
        {
            float cx = 0.f, cy = 0.f;
            #pragma unroll 4
            for (int r0 = 0; r0 < 32; r0++){
                int r = cq*32 + r0;
                uint32_t addr = cbase + (uint32_t)(r*128 + ((cg ^ (r&7))<<4));
                uint32_t raw;
                asm volatile("ld.shared.b32 %0, [%1];" : "=r"(raw) : "r"(addr));
                float2 f = __half22float2(*(__half2*)&raw);
                float w = sw[r];
                cx = fmaf(w, f.x, cx);
                cy = fmaf(w, f.y, cy);
            }
            sctx[cq*128 + cp] = make_float2(cx, cy);
        }
        __syncthreads();
        if (tid < 128){
            float2 a0 = sctx[tid], a1 = sctx[128+tid], a2 = sctx[256+tid], a3 = sctx[384+tid];
            float2 r;
            r.x = (a0.x+a1.x) + (a2.x+a3.x);
            r.y = (a0.y+a1.y) + (a2.y+a3.y);
            ((float2*)g_pctx)[tile*128 + tid] = r;
        }
        if (tid == 0) g_psum[tile] = wred[0]+wred[1]+wred[2]+wred[3];
    }
}

__global__ void k_inv(){
    int b = threadIdx.x;
    float s = 0.f;
    #pragma unroll
    for (int t = 0; t < 32; t++) s += g_psum[b*32 + t];
    g_inv[b] = 1.f / s;
}

__global__ void k_wout(float* __restrict__ outw){
    int i = blockIdx.x*256 + threadIdx.x;
    outw[i] = g_escore[i] * g_inv[i >> 12];
}

__global__ void k_red(float* __restrict__ outc){
    int b = blockIdx.x, d = threadIdx.x;
    float a = 0.f;
    #pragma unroll
    for (int t = 0; t < 32; t++) a += g_pctx[(b*32 + t)*VDIM + d];
    outc[b*VDIM + d] = a * g_inv[b];
}

extern "C" void kernel_launch(void* const* d_in, const int* in_sizes, int n_in,
                              void* d_out, int out_size){
    (void)in_sizes; (void)n_in; (void)out_size;
    const float* query  = (const float*)d_in[0];
    const float* values = (const float*)d_in[1];
    const float* W1 = (const float*)d_in[2];
    const float* b1 = (const float*)d_in[3];
    const float* W2 = (const float*)d_in[4];
    const float* b2 = (const float*)d_in[5];
    const float* Wv = (const float*)d_in[6];
    const float* bv = (const float*)d_in[7];
    float* out = (float*)d_out;
    cudaFuncSetAttribute(k_scores, cudaFuncAttributeMaxDynamicSharedMemorySize, SM_TOTAL);
    k_prep<<<BATCH + 1, 128>>>(query, W1, b1, W2, b2);
    k_scores<<<GRID_A, 512, SM_TOTAL>>>(values, Wv, bv);
    k_inv<<<1, BATCH>>>();
    k_wout<<<BATCH*SEQ/256, 256>>>(out + BATCH*VDIM);
    k_red<<<BATCH, VDIM>>>(out);
}

// round 11
// speedup vs baseline: 1.8491x; 1.4379x over previous
#include <cuda_runtime.h>
#include <cuda_fp16.h>
#include <cstdint>

#define UNITS 128
#define QDIM 256
#define VDIM 256
#define BATCH 128
#define SEQ 4096
#define TILE_M 128
#define N_TILES 4096
#define GRID_A 152

__device__ float g_qproj[BATCH*UNITS];
__device__ __half g_bhi[UNITS*VDIM];
__device__ float g_escore[BATCH*SEQ];
__device__ float g_psum[N_TILES];
__device__ float g_pctx[N_TILES*VDIM];

/* smem map (bytes) */
#define SM_BH 0
#define SM_A0 65536           /* 4 chunk buffers x 16384 */
#define SM_QROW 131072
#define SM_WV 131584
#define SM_SRED 132096
#define SM_WRED 133120
#define SM_SW 133184
#define SM_CTX 133696         /* 4 x 128 x float2 = 4096 */
#define SM_TOTAL 137792

#define LDSM4(f, addr) asm volatile( \
  "ldmatrix.sync.aligned.m8n8.x4.shared.b16 {%0,%1,%2,%3}, [%4];" \
  : "=r"((f)[0]),"=r"((f)[1]),"=r"((f)[2]),"=r"((f)[3]) : "r"(addr))

#define MMA(dd, aa, b0, b1) asm volatile( \
  "mma.sync.aligned.m16n8k16.row.col.f32.f16.f16.f32 {%0,%1,%2,%3}, {%4,%5,%6,%7}, {%8,%9}, {%0,%1,%2,%3};" \
  : "+f"((dd)[0]),"+f"((dd)[1]),"+f"((dd)[2]),"+f"((dd)[3]) \
  : "r"((aa)[0]),"r"((aa)[1]),"r"((aa)[2]),"r"((aa)[3]),"r"(b0),"r"(b1))

__device__ __forceinline__ uint32_t h2u(__half2 h){ return *(uint32_t*)&h; }

/* tanh via MUFU: 1 - 2/(1+e^{2x}) */
__device__ __forceinline__ float ftanh(float x){
    float e = __expf(2.0f * x);
    return 1.0f - __fdividef(2.0f, 1.0f + e);
}

__global__ void k_prep(const float* __restrict__ q, const float* __restrict__ W1,
                       const float* __restrict__ b1, const float* __restrict__ W2,
                       const float* __restrict__ b2){
    if (blockIdx.x < BATCH){
        int b = blockIdx.x, u = threadIdx.x;
        float acc = b1[u] + b2[u];
        #pragma unroll 8
        for (int k = 0; k < QDIM; k++) acc = fmaf(q[b*QDIM+k], W1[k*UNITS+u], acc);
        g_qproj[b*UNITS+u] = acc;
    } else {
        for (int i = threadIdx.x; i < UNITS*VDIM; i += 128){
            int u = i >> 8, k = i & 255;
            g_bhi[u*VDIM+k] = __float2half_rn(W2[k*UNITS+u]);
        }
    }
}

__global__ void __launch_bounds__(512,1)
k_scores(const float* __restrict__ values, const float* __restrict__ Wv, const float* __restrict__ bv){
    extern __shared__ char smem[];
    const int tid = threadIdx.x;
    const int lane = tid & 31;
    const int wid = tid >> 5;
    const int warp_m = wid & 7;   /* 8 groups x 16 rows */
    const int warp_n = wid >> 3;  /* 2 groups x 64 units */

    uint32_t sbase;
    asm("{ .reg .u64 t; cvta.to.shared.u64 t, %1; cvt.u32.u64 %0, t; }":"=r"(sbase):"l"(smem));

    /* stage B: [u][k] rows of 512B, XOR-swizzled 16B granules */
    #pragma unroll
    for (int j = 0; j < 8; j++){
        int G = j*512 + tid;
        int u = G >> 5, g = G & 31;
        int off = u*512 + ((g ^ (u&7))<<4);
        *(uint4*)(smem + SM_BH + off) = ((const uint4*)g_bhi)[G];
    }
    if (tid < UNITS) ((float*)(smem+SM_WV))[tid] = Wv[tid];
    const float bvv = bv[0];
    float* qrow = (float*)(smem+SM_QROW);
    float* wvs  = (float*)(smem+SM_WV);
    float* sred = (float*)(smem+SM_SRED);
    float* wred = (float*)(smem+SM_WRED);
    float* sw   = (float*)(smem+SM_SW);
    float2* sctx = (float2*)(smem+SM_CTX);

    /* ldmatrix address precompute */
    const int a_r = warp_m*16 + ((lane>>3)&1)*8 + (lane&7);
    const uint32_t a_base0 = sbase + SM_A0 + a_r*128;
    const int a_r7 = a_r & 7;
    const int gA_l = (lane>>4);
    uint32_t b_base[4]; int b_n7[4];
    #pragma unroll
    for (int nf2 = 0; nf2 < 4; nf2++){
        int n = warp_n*64 + nf2*16 + (lane>>4)*8 + (lane&7);
        b_base[nf2] = sbase + SM_BH + n*512;
        b_n7[nf2] = n & 7;
    }
    const int gB_l = ((lane>>3)&1);
    const int srow = tid >> 2;
    const int sq = tid & 3;

    /* context-phase mapping: dims (2p,2p+1), row quarter cq */
    const int cq = tid >> 7, cp = tid & 127;
    const uint32_t cbase = sbase + SM_A0 + (cp>>5)*16384 + ((cp&3)<<2);
    const int cg = (cp&31) >> 2;

    for (int tile = blockIdx.x; tile < N_TILES; tile += gridDim.x){
        const int b = tile >> 5, s0 = (tile & 31) * TILE_M;
        const float* vp = values + ((size_t)(b*SEQ + s0 + srow))*VDIM + sq*16;
        float4 v[4];
        #pragma unroll
        for (int j = 0; j < 4; j++) v[j] = ((const float4*)vp)[j];
        if (tid < 128) qrow[tid] = g_qproj[b*UNITS + tid];
        float d[8][4] = {};
        /* convert chunk 0 */
        #pragma unroll
        for (int i = 0; i < 2; i++){
            float4 p0 = v[2*i], p1 = v[2*i+1];
            __half2 h0=__floats2half2_rn(p0.x,p0.y), h1=__floats2half2_rn(p0.z,p0.w);
            __half2 h2=__floats2half2_rn(p1.x,p1.y), h3=__floats2half2_rn(p1.z,p1.w);
            int off = srow*128 + (((sq*2+i)^(srow&7))<<4);
            *(uint4*)(smem + SM_A0 + off) = make_uint4(h2u(h0),h2u(h1),h2u(h2),h2u(h3));
        }

        #pragma unroll
        for (int kc = 0; kc < 4; kc++){
            __syncthreads();
            if (kc < 3){
                const float* vp2 = vp + (kc+1)*64;
                #pragma unroll
                for (int j = 0; j < 4; j++) v[j] = ((const float4*)vp2)[j];
            }
            const uint32_t abase = a_base0 + (uint32_t)(kc*16384);
            #pragma unroll
            for (int ks = 0; ks < 4; ks++){
                uint32_t a[4];
                int gA = ks*2 + gA_l;
                LDSM4(a, abase + ((gA ^ a_r7)<<4));
                #pragma unroll
                for (int nf2 = 0; nf2 < 4; nf2++){
                    int gB = kc*8 + ks*2 + gB_l;
                    uint32_t bh[4];
                    LDSM4(bh, b_base[nf2] + ((gB ^ b_n7[nf2])<<4));
                    MMA(d[2*nf2],   a, bh[0], bh[1]);
                    MMA(d[2*nf2+1], a, bh[2], bh[3]);
                }
            }
            if (kc < 3){
                char* buf = smem + SM_A0 + (kc+1)*16384;
                #pragma unroll
                for (int i = 0; i < 2; i++){
                    float4 p0 = v[2*i], p1 = v[2*i+1];
                    __half2 h0=__floats2half2_rn(p0.x,p0.y), h1=__floats2half2_rn(p0.z,p0.w);
                    __half2 h2=__floats2half2_rn(p1.x,p1.y), h3=__floats2half2_rn(p1.z,p1.w);
                    int off = srow*128 + (((sq*2+i)^(srow&7))<<4);
                    *(uint4*)(buf + off) = make_uint4(h2u(h0),h2u(h1),h2u(h2),h2u(h3));
                }
            }
        }

        /* epilogue: score -> e */
        float part[2] = {0.f, 0.f};
        #pragma unroll
        for (int nf = 0; nf < 8; nf++)
            #pragma unroll
            for (int e = 0; e < 4; e++){
                int col = warp_n*64 + nf*8 + (lane&3)*2 + (e&1);
                float pre = d[nf][e] + qrow[col];
                part[e>>1] = fmaf(wvs[col], ftanh(pre), part[e>>1]);
            }
        #pragma unroll
        for (int p = 0; p < 2; p++){
            part[p] += __shfl_xor_sync(0xffffffffu, part[p], 1);
            part[p] += __shfl_xor_sync(0xffffffffu, part[p], 2);
        }
        if ((lane & 3) == 0){
            #pragma unroll
            for (int p = 0; p < 2; p++){
                int row = warp_m*16 + (lane>>2) + p*8;
                sred[warp_n*128 + row] = part[p];
            }
        }
        __syncthreads();
        if (tid < 128){
            float e = __expf(sred[tid] + sred[128+tid] + bvv);
            g_escore[b*SEQ + s0 + tid] = e;
            sw[tid] = e;
            #pragma unroll
            for (int o = 16; o; o >>= 1) e += __shfl_xor_sync(0xffffffffu, e, o);
            if (lane == 0) wred[tid>>5] = e;
        }
        __syncthreads();

        /* fused context: pctx[d] = sum_r e_r * v_hi[r][d] (from A smem) */
        {
            float cx = 0.f, cy = 0.f;
            #pragma unroll 4
            for (int r0 = 0; r0 < 32; r0++){
                int r = cq*32 + r0;
                uint32_t addr = cbase + (uint32_t)(r*128 + ((cg ^ (r&7))<<4));
                uint32_t raw;
                asm volatile("ld.shared.b32 %0, [%1];" : "=r"(raw) : "r"(addr));
                float2 f = __half22float2(*(__half2*)&raw);
                float w = sw[r];
                cx = fmaf(w, f.x, cx);
                cy = fmaf(w, f.y, cy);
            }
            sctx[cq*128 + cp] = make_float2(cx, cy);
        }
        __syncthreads();
        if (tid < 128){
            float2 a0 = sctx[tid], a1 = sctx[128+tid], a2 = sctx[256+tid], a3 = sctx[384+tid];
            float2 r;
            r.x = (a0.x+a1.x) + (a2.x+a3.x);
            r.y = (a0.y+a1.y) + (a2.y+a3.y);
            ((float2*)g_pctx)[tile*128 + tid] = r;
        }
        if (tid == 0) g_psum[tile] = wred[0]+wred[1]+wred[2]+wred[3];
    }
}

__global__ void __launch_bounds__(256)
k_wout(float* __restrict__ outw){
    __shared__ float sinv;
    int i = blockIdx.x*256 + threadIdx.x;
    int b = i >> 12;
    if (threadIdx.x < 32){
        float s = g_psum[b*32 + threadIdx.x];
        #pragma unroll
        for (int o = 16; o; o >>= 1) s += __shfl_xor_sync(0xffffffffu, s, o);
        if (threadIdx.x == 0) sinv = 1.f / s;
    }
    __syncthreads();
    outw[i] = g_escore[i] * sinv;
}

__global__ void __launch_bounds__(256)
k_red(float* __restrict__ outc){
    __shared__ float sinv;
    int b = blockIdx.x, d = threadIdx.x;
    if (threadIdx.x < 32){
        float s = g_psum[b*32 + threadIdx.x];
        #pragma unroll
        for (int o = 16; o; o >>= 1) s += __shfl_xor_sync(0xffffffffu, s, o);
        if (threadIdx.x == 0) sinv = 1.f / s;
    }
    __syncthreads();
    float a = 0.f;
    #pragma unroll
    for (int t = 0; t < 32; t++) a += g_pctx[(b*32 + t)*VDIM + d];
    outc[b*VDIM + d] = a * sinv;
}

extern "C" void kernel_launch(void* const* d_in, const int* in_sizes, int n_in,
                              void* d_out, int out_size){
    (void)in_sizes; (void)n_in; (void)out_size;
    const float* query  = (const float*)d_in[0];
    const float* values = (const float*)d_in[1];
    const float* W1 = (const float*)d_in[2];
    const float* b1 = (const float*)d_in[3];
    const float* W2 = (const float*)d_in[4];
    const float* b2 = (const float*)d_in[5];
    const float* Wv = (const float*)d_in[6];
    const float* bv = (const float*)d_in[7];
    float* out = (float*)d_out;
    cudaFuncSetAttribute(k_scores, cudaFuncAttributeMaxDynamicSharedMemorySize, SM_TOTAL);
    k_prep<<<BATCH + 1, 128>>>(query, W1, b1, W2, b2);
    k_scores<<<GRID_A, 512, SM_TOTAL>>>(values, Wv, bv);
    k_wout<<<BATCH*SEQ/256, 256>>>(out + BATCH*VDIM);
    k_red<<<BATCH, VDIM>>>(out);
}

// round 12
// speedup vs baseline: 2.0912x; 1.1309x over previous
#include <cuda_runtime.h>
#include <cuda_fp16.h>
#include <cstdint>

#define UNITS 128
#define QDIM 256
#define VDIM 256
#define BATCH 128
#define SEQ 4096
#define TM 64                 /* rows per tile */
#define NT2 8192              /* BATCH*SEQ/TM */
#define GRID_A 304

__device__ float g_qproj[BATCH*UNITS];
__device__ __half g_bhi[UNITS*VDIM];
__device__ float g_escore[BATCH*SEQ];
__device__ float g_psum[NT2];
__device__ float g_pctx[NT2*VDIM];

/* smem map (bytes) per CTA */
#define SM_BH 0               /* 64 KB */
#define SM_A0 65536           /* 4 chunk buffers x 8192 (64 rows x 128B) */
#define SM_QROW 98304
#define SM_WV 98816
#define SM_SRED 99328         /* 2 x 64 floats */
#define SM_WRED 99840
#define SM_SW 99904           /* 64 floats */
#define SM_CTX 100160         /* 2 x 128 float2 */
#define SM_TOTAL 102208

#define LDSM4(f, addr) asm volatile( \
  "ldmatrix.sync.aligned.m8n8.x4.shared.b16 {%0,%1,%2,%3}, [%4];" \
  : "=r"((f)[0]),"=r"((f)[1]),"=r"((f)[2]),"=r"((f)[3]) : "r"(addr))

#define MMA(dd, aa, b0, b1) asm volatile( \
  "mma.sync.aligned.m16n8k16.row.col.f32.f16.f16.f32 {%0,%1,%2,%3}, {%4,%5,%6,%7}, {%8,%9}, {%0,%1,%2,%3};" \
  : "+f"((dd)[0]),"+f"((dd)[1]),"+f"((dd)[2]),"+f"((dd)[3]) \
  : "r"((aa)[0]),"r"((aa)[1]),"r"((aa)[2]),"r"((aa)[3]),"r"(b0),"r"(b1))

__device__ __forceinline__ uint32_t h2u(__half2 h){ return *(uint32_t*)&h; }

/* HW tanh (MUFU.TANH), rel err ~2^-11 */
__device__ __forceinline__ float ftanh(float x){
    float y; asm("tanh.approx.f32 %0, %1;" : "=f"(y) : "f"(x)); return y;
}

__global__ void k_prep(const float* __restrict__ q, const float* __restrict__ W1,
                       const float* __restrict__ b1, const float* __restrict__ W2,
                       const float* __restrict__ b2){
    if (blockIdx.x < BATCH){
        int b = blockIdx.x, u = threadIdx.x;
        float acc = b1[u] + b2[u];
        #pragma unroll 8
        for (int k = 0; k < QDIM; k++) acc = fmaf(q[b*QDIM+k], W1[k*UNITS+u], acc);
        g_qproj[b*UNITS+u] = acc;
    } else {
        for (int i = threadIdx.x; i < UNITS*VDIM; i += 128){
            int u = i >> 8, k = i & 255;
            g_bhi[u*VDIM+k] = __float2half_rn(W2[k*UNITS+u]);
        }
    }
}

__global__ void __launch_bounds__(256,2)
k_scores(const float* __restrict__ values, const float* __restrict__ Wv, const float* __restrict__ bv){
    extern __shared__ char smem[];
    const int tid = threadIdx.x;
    const int lane = tid & 31;
    const int wid = tid >> 5;
    const int warp_m = wid & 3;   /* 4 groups x 16 rows */
    const int warp_n = wid >> 2;  /* 2 groups x 64 units */

    uint32_t sbase;
    asm("{ .reg .u64 t; cvta.to.shared.u64 t, %1; cvt.u32.u64 %0, t; }":"=r"(sbase):"l"(smem));

    /* stage B: [u][k] rows of 512B, XOR-swizzled 16B granules */
    #pragma unroll
    for (int j = 0; j < 16; j++){
        int G = j*256 + tid;
        int u = G >> 5, g = G & 31;
        int off = u*512 + ((g ^ (u&7))<<4);
        *(uint4*)(smem + SM_BH + off) = ((const uint4*)g_bhi)[G];
    }
    if (tid < UNITS) ((float*)(smem+SM_WV))[tid] = Wv[tid];
    const float bvv = bv[0];
    float* qrow = (float*)(smem+SM_QROW);
    float* wvs  = (float*)(smem+SM_WV);
    float* sred = (float*)(smem+SM_SRED);
    float* wred = (float*)(smem+SM_WRED);
    float* sw   = (float*)(smem+SM_SW);
    float2* sctx = (float2*)(smem+SM_CTX);

    /* ldmatrix address precompute */
    const int a_r = warp_m*16 + ((lane>>3)&1)*8 + (lane&7);
    const uint32_t a_base0 = sbase + SM_A0 + a_r*128;
    const int a_r7 = a_r & 7;
    const int gA_l = (lane>>4);
    uint32_t b_base[4]; int b_n7[4];
    #pragma unroll
    for (int nf2 = 0; nf2 < 4; nf2++){
        int n = warp_n*64 + nf2*16 + (lane>>4)*8 + (lane&7);
        b_base[nf2] = sbase + SM_BH + n*512;
        b_n7[nf2] = n & 7;
    }
    const int gB_l = ((lane>>3)&1);
    /* staging: 4 threads per row, 16 cols each */
    const int srow = tid >> 2;
    const int sq = tid & 3;
    const int soff = srow*128 + (((sq*2) ^ (srow&7))<<4);
    const int soff2 = srow*128 + (((sq*2+1) ^ (srow&7))<<4);

    /* context mapping: dims (2cp,2cp+1), row half cq */
    const int cq = tid >> 7, cp = tid & 127;
    const uint32_t cbase = sbase + SM_A0 + (cp>>5)*8192 + ((cp&3)<<2);
    const int cg = (cp&31) >> 2;

    int tile = blockIdx.x;
    float4 pv[4];
    {   /* preload chunk 0 of first tile */
        const int b = tile >> 6, s0 = (tile & 63) * TM;
        const float* vp0 = values + ((size_t)(b*SEQ + s0 + srow))*VDIM + sq*16;
        #pragma unroll
        for (int j = 0; j < 4; j++) pv[j] = ((const float4*)vp0)[j];
    }

    for (; tile < NT2; tile += GRID_A){
        const int b = tile >> 6, s0 = (tile & 63) * TM;
        const float* vp = values + ((size_t)(b*SEQ + s0 + srow))*VDIM + sq*16;
        if (tid < 128) qrow[tid] = g_qproj[b*UNITS + tid];
        float d[8][4] = {};
        /* convert prefetched chunk 0 */
        {
            float4 p0 = pv[0], p1 = pv[1], p2 = pv[2], p3 = pv[3];
            __half2 h0=__floats2half2_rn(p0.x,p0.y), h1=__floats2half2_rn(p0.z,p0.w);
            __half2 h2=__floats2half2_rn(p1.x,p1.y), h3=__floats2half2_rn(p1.z,p1.w);
            __half2 h4=__floats2half2_rn(p2.x,p2.y), h5=__floats2half2_rn(p2.z,p2.w);
            __half2 h6=__floats2half2_rn(p3.x,p3.y), h7=__floats2half2_rn(p3.z,p3.w);
            *(uint4*)(smem + SM_A0 + soff)  = make_uint4(h2u(h0),h2u(h1),h2u(h2),h2u(h3));
            *(uint4*)(smem + SM_A0 + soff2) = make_uint4(h2u(h4),h2u(h5),h2u(h6),h2u(h7));
        }

        #pragma unroll
        for (int kc = 0; kc < 4; kc++){
            __syncthreads();
            float4 v[4];
            if (kc < 3){
                const float* vp2 = vp + (kc+1)*64;
                #pragma unroll
                for (int j = 0; j < 4; j++) v[j] = ((const float4*)vp2)[j];
            }
            const uint32_t abase = a_base0 + (uint32_t)(kc*8192);
            #pragma unroll
            for (int ks = 0; ks < 4; ks++){
                uint32_t a[4];
                int gA = ks*2 + gA_l;
                LDSM4(a, abase + ((gA ^ a_r7)<<4));
                #pragma unroll
                for (int nf2 = 0; nf2 < 4; nf2++){
                    int gB = kc*8 + ks*2 + gB_l;
                    uint32_t bh[4];
                    LDSM4(bh, b_base[nf2] + ((gB ^ b_n7[nf2])<<4));
                    MMA(d[2*nf2],   a, bh[0], bh[1]);
                    MMA(d[2*nf2+1], a, bh[2], bh[3]);
                }
            }
            if (kc < 3){
                char* buf = smem + SM_A0 + (kc+1)*8192;
                float4 p0 = v[0], p1 = v[1], p2 = v[2], p3 = v[3];
                __half2 h0=__floats2half2_rn(p0.x,p0.y), h1=__floats2half2_rn(p0.z,p0.w);
                __half2 h2=__floats2half2_rn(p1.x,p1.y), h3=__floats2half2_rn(p1.z,p1.w);
                __half2 h4=__floats2half2_rn(p2.x,p2.y), h5=__floats2half2_rn(p2.z,p2.w);
                __half2 h6=__floats2half2_rn(p3.x,p3.y), h7=__floats2half2_rn(p3.z,p3.w);
                *(uint4*)(buf + soff)  = make_uint4(h2u(h0),h2u(h1),h2u(h2),h2u(h3));
                *(uint4*)(buf + soff2) = make_uint4(h2u(h4),h2u(h5),h2u(h6),h2u(h7));
            }
        }

        /* prefetch next tile's chunk 0 (hidden behind epilogue+ctx) */
        {
            int nt = tile + GRID_A;
            if (nt < NT2){
                const int b2 = nt >> 6, s02 = (nt & 63) * TM;
                const float* vpn = values + ((size_t)(b2*SEQ + s02 + srow))*VDIM + sq*16;
                #pragma unroll
                for (int j = 0; j < 4; j++) pv[j] = ((const float4*)vpn)[j];
            }
        }

        /* epilogue: score -> e */
        float part[2] = {0.f, 0.f};
        #pragma unroll
        for (int nf = 0; nf < 8; nf++)
            #pragma unroll
            for (int e = 0; e < 4; e++){
                int col = warp_n*64 + nf*8 + (lane&3)*2 + (e&1);
                float pre = d[nf][e] + qrow[col];
                part[e>>1] = fmaf(wvs[col], ftanh(pre), part[e>>1]);
            }
        #pragma unroll
        for (int p = 0; p < 2; p++){
            part[p] += __shfl_xor_sync(0xffffffffu, part[p], 1);
            part[p] += __shfl_xor_sync(0xffffffffu, part[p], 2);
        }
        if ((lane & 3) == 0){
            #pragma unroll
            for (int p = 0; p < 2; p++){
                int row = warp_m*16 + (lane>>2) + p*8;
                sred[warp_n*64 + row] = part[p];
            }
        }
        __syncthreads();
        if (tid < TM){
            float e = __expf(sred[tid] + sred[64+tid] + bvv);
            g_escore[b*SEQ + s0 + tid] = e;
            sw[tid] = e;
            #pragma unroll
            for (int o = 16; o; o >>= 1) e += __shfl_xor_sync(0xffffffffu, e, o);
            if (lane == 0) wred[tid>>5] = e;
        }
        __syncthreads();

        /* fused context from A smem (fp16 hi values) */
        {
            float cx = 0.f, cy = 0.f;
            #pragma unroll 4
            for (int r0 = 0; r0 < 32; r0++){
                int r = cq*32 + r0;
                uint32_t addr = cbase + (uint32_t)(r*128 + ((cg ^ (r&7))<<4));
                uint32_t raw;
                asm volatile("ld.shared.b32 %0, [%1];" : "=r"(raw) : "r"(addr));
                float2 f = __half22float2(*(__half2*)&raw);
                float w = sw[r];
                cx = fmaf(w, f.x, cx);
                cy = fmaf(w, f.y, cy);
            }
            sctx[cq*128 + cp] = make_float2(cx, cy);
        }
        __syncthreads();
        if (tid < 128){
            float2 a0 = sctx[tid], a1 = sctx[128+tid];
            ((float2*)g_pctx)[tile*128 + tid] = make_float2(a0.x+a1.x, a0.y+a1.y);
        }
        if (tid == 0) g_psum[tile] = wred[0]+wred[1];
    }
}

__global__ void __launch_bounds__(256)
k_wout(float* __restrict__ outw){
    __shared__ float wsum[2];
    int i = blockIdx.x*256 + threadIdx.x;
    int b = (blockIdx.x*256) >> 12;
    if (threadIdx.x < 64){
        float s = g_psum[b*64 + threadIdx.x];
        #pragma unroll
        for (int o = 16; o; o >>= 1) s += __shfl_xor_sync(0xffffffffu, s, o);
        if ((threadIdx.x & 31) == 0) wsum[threadIdx.x>>5] = s;
    }
    __syncthreads();
    outw[i] = g_escore[i] * (1.f / (wsum[0] + wsum[1]));
}

__global__ void __launch_bounds__(512)
k_red(float* __restrict__ outc){
    __shared__ float wsum[2];
    __shared__ float sp[512];
    int b = blockIdx.x;
    int tid = threadIdx.x;
    if (tid < 64){
        float s = g_psum[b*64 + tid];
        #pragma unroll
        for (int o = 16; o; o >>= 1) s += __shfl_xor_sync(0xffffffffu, s, o);
        if ((tid & 31) == 0) wsum[tid>>5] = s;
    }
    int d = tid & 255, h = tid >> 8;
    float a = 0.f;
    #pragma unroll
    for (int t = 0; t < 32; t++) a += g_pctx[(b*64 + h*32 + t)*VDIM + d];
    sp[tid] = a;
    __syncthreads();
    if (tid < 256)
        outc[b*VDIM + tid] = (sp[tid] + sp[tid+256]) * (1.f / (wsum[0] + wsum[1]));
}

extern "C" void kernel_launch(void* const* d_in, const int* in_sizes, int n_in,
                              void* d_out, int out_size){
    (void)in_sizes; (void)n_in; (void)out_size;
    const float* query  = (const float*)d_in[0];
    const float* values = (const float*)d_in[1];
    const float* W1 = (const float*)d_in[2];
    const float* b1 = (const float*)d_in[3];
    const float* W2 = (const float*)d_in[4];
    const float* b2 = (const float*)d_in[5];
    const float* Wv = (const float*)d_in[6];
    const float* bv = (const float*)d_in[7];
    float* out = (float*)d_out;
    cudaFuncSetAttribute(k_scores, cudaFuncAttributeMaxDynamicSharedMemorySize, SM_TOTAL);
    k_prep<<<BATCH + 1, 128>>>(query, W1, b1, W2, b2);
    k_scores<<<GRID_A, 256, SM_TOTAL>>>(values, Wv, bv);
    k_wout<<<BATCH*SEQ/256, 256>>>(out + BATCH*VDIM);
    k_red<<<BATCH, 512>>>(out);
}

// round 13
// speedup vs baseline: 2.2241x; 1.0636x over previous
#include <cuda_runtime.h>
#include <cuda_fp16.h>
#include <cstdint>

#define UNITS 128
#define QDIM 256
#define VDIM 256
#define BATCH 128
#define SEQ 4096
#define TM 64
#define NT2 8192
#define GRID_A 304

__device__ float g_qproj[BATCH*UNITS];
__device__ __half g_bhi[UNITS*VDIM];
__device__ float g_escore[BATCH*SEQ];
__device__ float g_psum[NT2];
__device__ float g_pctx[NT2*VDIM];

/* smem map (bytes) per CTA */
#define SM_BH 0               /* 64 KB */
#define SM_A0 65536           /* 4 chunk buffers x 8192 */
#define SM_QROW 98304
#define SM_WV 98816
#define SM_SRED 99328
#define SM_WRED 99840
#define SM_SW 99904
#define SM_CTX 100160         /* 8 x 256 floats = 8192 */
#define SM_TOTAL 108352

#define LDSM4(f, addr) asm volatile( \
  "ldmatrix.sync.aligned.m8n8.x4.shared.b16 {%0,%1,%2,%3}, [%4];" \
  : "=r"((f)[0]),"=r"((f)[1]),"=r"((f)[2]),"=r"((f)[3]) : "r"(addr))

/* fp16-accumulator MMA */
#define MMAH(dd, aa, b0, b1) asm volatile( \
  "mma.sync.aligned.m16n8k16.row.col.f16.f16.f16.f16 {%0,%1}, {%2,%3,%4,%5}, {%6,%7}, {%0,%1};" \
  : "+r"((dd)[0]),"+r"((dd)[1]) \
  : "r"((aa)[0]),"r"((aa)[1]),"r"((aa)[2]),"r"((aa)[3]),"r"(b0),"r"(b1))

__device__ __forceinline__ uint32_t h2u(__half2 h){ return *(uint32_t*)&h; }

__device__ __forceinline__ float ftanh(float x){
    float y; asm("tanh.approx.f32 %0, %1;" : "=f"(y) : "f"(x)); return y;
}

__global__ void k_prep(const float* __restrict__ q, const float* __restrict__ W1,
                       const float* __restrict__ b1, const float* __restrict__ W2,
                       const float* __restrict__ b2){
    if (blockIdx.x < BATCH){
        int b = blockIdx.x, u = threadIdx.x;
        float acc = b1[u] + b2[u];
        #pragma unroll 8
        for (int k = 0; k < QDIM; k++) acc = fmaf(q[b*QDIM+k], W1[k*UNITS+u], acc);
        g_qproj[b*UNITS+u] = acc;
    } else {
        for (int i = threadIdx.x; i < UNITS*VDIM; i += 128){
            int u = i >> 8, k = i & 255;
            g_bhi[u*VDIM+k] = __float2half_rn(W2[k*UNITS+u]);
        }
    }
}

__global__ void __launch_bounds__(256,2)
k_scores(const float* __restrict__ values, const float* __restrict__ Wv, const float* __restrict__ bv){
    extern __shared__ char smem[];
    const int tid = threadIdx.x;
    const int lane = tid & 31;
    const int wid = tid >> 5;
    const int warp_m = wid & 3;
    const int warp_n = wid >> 2;

    uint32_t sbase;
    asm("{ .reg .u64 t; cvta.to.shared.u64 t, %1; cvt.u32.u64 %0, t; }":"=r"(sbase):"l"(smem));

    #pragma unroll
    for (int j = 0; j < 16; j++){
        int G = j*256 + tid;
        int u = G >> 5, g = G & 31;
        int off = u*512 + ((g ^ (u&7))<<4);
        *(uint4*)(smem + SM_BH + off) = ((const uint4*)g_bhi)[G];
    }
    if (tid < UNITS) ((float*)(smem+SM_WV))[tid] = Wv[tid];
    const float bvv = bv[0];
    float* qrow = (float*)(smem+SM_QROW);
    float* wvs  = (float*)(smem+SM_WV);
    float* sred = (float*)(smem+SM_SRED);
    float* wred = (float*)(smem+SM_WRED);
    float* sw   = (float*)(smem+SM_SW);
    float* sctx = (float*)(smem+SM_CTX);

    const int a_r = warp_m*16 + ((lane>>3)&1)*8 + (lane&7);
    const uint32_t a_base0 = sbase + SM_A0 + a_r*128;
    const int a_r7 = a_r & 7;
    const int gA_l = (lane>>4);
    uint32_t b_base[4]; int b_n7[4];
    #pragma unroll
    for (int nf2 = 0; nf2 < 4; nf2++){
        int n = warp_n*64 + nf2*16 + (lane>>4)*8 + (lane&7);
        b_base[nf2] = sbase + SM_BH + n*512;
        b_n7[nf2] = n & 7;
    }
    const int gB_l = ((lane>>3)&1);
    const int srow = tid >> 2;
    const int sq = tid & 3;
    const int soff = srow*128 + (((sq*2) ^ (srow&7))<<4);
    const int soff2 = srow*128 + (((sq*2+1) ^ (srow&7))<<4);

    /* context mapping: 8 dims x 8 rows per thread */
    const int cg8 = tid & 31;           /* dim group: dims [8*cg8, 8*cg8+8) */
    const int rq = tid >> 5;            /* row group: rows [8*rq, 8*rq+8) */
    const uint32_t ctx_base = sbase + SM_A0 + (cg8>>3)*8192;
    const int ctx_gr = cg8 & 7;

    int tile = blockIdx.x;
    float4 pv[4];
    {
        const int b = tile >> 6, s0 = (tile & 63) * TM;
        const float* vp0 = values + ((size_t)(b*SEQ + s0 + srow))*VDIM + sq*16;
        #pragma unroll
        for (int j = 0; j < 4; j++) pv[j] = ((const float4*)vp0)[j];
    }

    for (; tile < NT2; tile += GRID_A){
        const int b = tile >> 6, s0 = (tile & 63) * TM;
        const float* vp = values + ((size_t)(b*SEQ + s0 + srow))*VDIM + sq*16;
        if (tid < 128) qrow[tid] = g_qproj[b*UNITS + tid];
        uint32_t d[8][2] = {};
        {
            float4 p0 = pv[0], p1 = pv[1], p2 = pv[2], p3 = pv[3];
            __half2 h0=__floats2half2_rn(p0.x,p0.y), h1=__floats2half2_rn(p0.z,p0.w);
            __half2 h2=__floats2half2_rn(p1.x,p1.y), h3=__floats2half2_rn(p1.z,p1.w);
            __half2 h4=__floats2half2_rn(p2.x,p2.y), h5=__floats2half2_rn(p2.z,p2.w);
            __half2 h6=__floats2half2_rn(p3.x,p3.y), h7=__floats2half2_rn(p3.z,p3.w);
            *(uint4*)(smem + SM_A0 + soff)  = make_uint4(h2u(h0),h2u(h1),h2u(h2),h2u(h3));
            *(uint4*)(smem + SM_A0 + soff2) = make_uint4(h2u(h4),h2u(h5),h2u(h6),h2u(h7));
        }

        #pragma unroll
        for (int kc = 0; kc < 4; kc++){
            __syncthreads();
            float4 v[4];
            if (kc < 3){
                const float* vp2 = vp + (kc+1)*64;
                #pragma unroll
                for (int j = 0; j < 4; j++) v[j] = ((const float4*)vp2)[j];
            }
            const uint32_t abase = a_base0 + (uint32_t)(kc*8192);
            #pragma unroll
            for (int ks = 0; ks < 4; ks++){
                uint32_t a[4];
                int gA = ks*2 + gA_l;
                LDSM4(a, abase + ((gA ^ a_r7)<<4));
                #pragma unroll
                for (int nf2 = 0; nf2 < 4; nf2++){
                    int gB = kc*8 + ks*2 + gB_l;
                    uint32_t bh[4];
                    LDSM4(bh, b_base[nf2] + ((gB ^ b_n7[nf2])<<4));
                    MMAH(d[2*nf2],   a, bh[0], bh[1]);
                    MMAH(d[2*nf2+1], a, bh[2], bh[3]);
                }
            }
            if (kc < 3){
                char* buf = smem + SM_A0 + (kc+1)*8192;
                float4 p0 = v[0], p1 = v[1], p2 = v[2], p3 = v[3];
                __half2 h0=__floats2half2_rn(p0.x,p0.y), h1=__floats2half2_rn(p0.z,p0.w);
                __half2 h2=__floats2half2_rn(p1.x,p1.y), h3=__floats2half2_rn(p1.z,p1.w);
                __half2 h4=__floats2half2_rn(p2.x,p2.y), h5=__floats2half2_rn(p2.z,p2.w);
                __half2 h6=__floats2half2_rn(p3.x,p3.y), h7=__floats2half2_rn(p3.z,p3.w);
                *(uint4*)(buf + soff)  = make_uint4(h2u(h0),h2u(h1),h2u(h2),h2u(h3));
                *(uint4*)(buf + soff2) = make_uint4(h2u(h4),h2u(h5),h2u(h6),h2u(h7));
            }
        }

        /* prefetch next tile's chunk 0 */
        {
            int nt = tile + GRID_A;
            if (nt < NT2){
                const int b2 = nt >> 6, s02 = (nt & 63) * TM;
                const float* vpn = values + ((size_t)(b2*SEQ + s02 + srow))*VDIM + sq*16;
                #pragma unroll
                for (int j = 0; j < 4; j++) pv[j] = ((const float4*)vpn)[j];
            }
        }

        /* epilogue: score -> e */
        float part[2] = {0.f, 0.f};
        #pragma unroll
        for (int nf = 0; nf < 8; nf++){
            int col = warp_n*64 + nf*8 + (lane&3)*2;
            #pragma unroll
            for (int p = 0; p < 2; p++){
                float2 f = __half22float2(*(__half2*)&d[nf][p]);
                part[p] = fmaf(wvs[col],   ftanh(f.x + qrow[col]),   part[p]);
                part[p] = fmaf(wvs[col+1], ftanh(f.y + qrow[col+1]), part[p]);
            }
        }
        #pragma unroll
        for (int p = 0; p < 2; p++){
            part[p] += __shfl_xor_sync(0xffffffffu, part[p], 1);
            part[p] += __shfl_xor_sync(0xffffffffu, part[p], 2);
        }
        if ((lane & 3) == 0){
            #pragma unroll
            for (int p = 0; p < 2; p++){
                int row = warp_m*16 + (lane>>2) + p*8;
                sred[warp_n*64 + row] = part[p];
            }
        }
        __syncthreads();
        if (tid < TM){
            float e = __expf(sred[tid] + sred[64+tid] + bvv);
            g_escore[b*SEQ + s0 + tid] = e;
            sw[tid] = e;
            #pragma unroll
            for (int o = 16; o; o >>= 1) e += __shfl_xor_sync(0xffffffffu, e, o);
            if (lane == 0) wred[tid>>5] = e;
        }
        __syncthreads();

        /* fused context: vectorized, 8 dims x 8 rows per thread */
        {
            float acc[8] = {};
            #pragma unroll
            for (int r0 = 0; r0 < 8; r0++){
                int r = rq*8 + r0;
                uint32_t addr = ctx_base + (uint32_t)(r*128 + ((ctx_gr ^ (r&7))<<4));
                uint4 u;
                asm volatile("ld.shared.v4.b32 {%0,%1,%2,%3}, [%4];"
                    : "=r"(u.x),"=r"(u.y),"=r"(u.z),"=r"(u.w) : "r"(addr));
                float w = sw[r];
                float2 f0 = __half22float2(*(__half2*)&u.x);
                float2 f1 = __half22float2(*(__half2*)&u.y);
                float2 f2 = __half22float2(*(__half2*)&u.z);
                float2 f3 = __half22float2(*(__half2*)&u.w);
                acc[0] = fmaf(w, f0.x, acc[0]); acc[1] = fmaf(w, f0.y, acc[1]);
                acc[2] = fmaf(w, f1.x, acc[2]); acc[3] = fmaf(w, f1.y, acc[3]);
                acc[4] = fmaf(w, f2.x, acc[4]); acc[5] = fmaf(w, f2.y, acc[5]);
                acc[6] = fmaf(w, f3.x, acc[6]); acc[7] = fmaf(w, f3.y, acc[7]);
            }
            float* dst = sctx + rq*256 + cg8*8;
            *(float4*)dst = make_float4(acc[0],acc[1],acc[2],acc[3]);
            *(float4*)(dst+4) = make_float4(acc[4],acc[5],acc[6],acc[7]);
        }
        __syncthreads();
        if (tid < 128){
            float2* sc = (float2*)sctx;
            float2 a = sc[tid];
            #pragma unroll
            for (int q = 1; q < 8; q++){
                float2 t = sc[q*128 + tid];
                a.x += t.x; a.y += t.y;
            }
            ((float2*)g_pctx)[tile*128 + tid] = a;
        }
        if (tid == 0) g_psum[tile] = wred[0]+wred[1];
    }
}

__global__ void __launch_bounds__(256)
k_wout(float* __restrict__ outw){
    __shared__ float wsum[2];
    int i = blockIdx.x*256 + threadIdx.x;
    int b = (blockIdx.x*256) >> 12;
    if (threadIdx.x < 64){
        float s = g_psum[b*64 + threadIdx.x];
        #pragma unroll
        for (int o = 16; o; o >>= 1) s += __shfl_xor_sync(0xffffffffu, s, o);
        if ((threadIdx.x & 31) == 0) wsum[threadIdx.x>>5] = s;
    }
    __syncthreads();
    outw[i] = g_escore[i] * (1.f / (wsum[0] + wsum[1]));
}

__global__ void __launch_bounds__(512)
k_red(float* __restrict__ outc){
    __shared__ float wsum[2];
    __shared__ float sp[512];
    int b = blockIdx.x;
    int tid = threadIdx.x;
    if (tid < 64){
        float s = g_psum[b*64 + tid];
        #pragma unroll
        for (int o = 16; o; o >>= 1) s += __shfl_xor_sync(0xffffffffu, s, o);
        if ((tid & 31) == 0) wsum[tid>>5] = s;
    }
    int d = tid & 255, h = tid >> 8;
    float a = 0.f;
    #pragma unroll
    for (int t = 0; t < 32; t++) a += g_pctx[(b*64 + h*32 + t)*VDIM + d];
    sp[tid] = a;
    __syncthreads();
    if (tid < 256)
        outc[b*VDIM + tid] = (sp[tid] + sp[tid+256]) * (1.f / (wsum[0] + wsum[1]));
}

extern "C" void kernel_launch(void* const* d_in, const int* in_sizes, int n_in,
                              void* d_out, int out_size){
    (void)in_sizes; (void)n_in; (void)out_size;
    const float* query  = (const float*)d_in[0];
    const float* values = (const float*)d_in[1];
    const float* W1 = (const float*)d_in[2];
    const float* b1 = (const float*)d_in[3];
    const float* W2 = (const float*)d_in[4];
    const float* b2 = (const float*)d_in[5];
    const float* Wv = (const float*)d_in[6];
    const float* bv = (const float*)d_in[7];
    float* out = (float*)d_out;
    cudaFuncSetAttribute(k_scores, cudaFuncAttributeMaxDynamicSharedMemorySize, SM_TOTAL);
    k_prep<<<BATCH + 1, 128>>>(query, W1, b1, W2, b2);
    k_scores<<<GRID_A, 256, SM_TOTAL>>>(values, Wv, bv);
    k_wout<<<BATCH*SEQ/256, 256>>>(out + BATCH*VDIM);
    k_red<<<BATCH, 512>>>(out);
}